// round 14
// baseline (speedup 1.0000x reference)
#include <cuda_runtime.h>
#include <cuda_fp16.h>
#include <cstdint>

// ---------------- problem constants ----------------
#define Bb 16
#define Nn 128
#define Mm 1024
#define DNd 512
#define DEe 256
#define Pp 512
#define LR_OUT 9
#define CR_OUT 6
#define MR_OUT 17

// ---------------- scratch layout (float units) ----------------
#define OFF_OFFS 0LL          // 26624 long longs = 53248 floats
#define LLO_N    0
#define LLO_E    2048
#define LLO_P    18432
#define OFF_T1XP 53248LL      // (2048,256) f32 : T1 cols 0:128, XP cols 128:256  -> end 577536
#define OFF_T2   577536LL     // (16384,128) f32                                  -> end 2674688
#define OFF_HA   2674688LL    // (2048,256) f32 : H cols 0:128, AGG cols 128:256  -> end 3198976
#define OFF_HAW  3198976LL    // (2048,768) f32                                   -> end 4771840
#define OFF_QP   4771840LL    // (8192,128) half = 524288 f                       -> end 5296128
#define OFF_HID  5296128LL    // (8192,768) half = 3145728 f                      -> end 8441856
#define OFF_WNT  8441856LL    // (256,512) half = 65536 f                         -> end 8507392
#define OFF_WET  8507392LL    // (128,256) half = 16384 f                         -> end 8523776
#define OFF_WE2T 8523776LL    // (128,256) half = 16384 f                         -> end 8540160
#define OFF_W1AT 8540160LL    // (768,256) half = 98304 f                         -> end 8638464
#define OFF_W1BT 8638464LL    // (768,256) half = 98304 f                         -> end 8736768
#define OFF_W2T  8736768LL    // (32,768) half = 12288 f                          -> end 8749056
#define OFF_B1C  8749056LL    // 768 f32                                          -> end 8749824
#define OFF_B2C  8749824LL    // 32 f32                                           -> end 8749856
#define SCRATCH_TOTAL 8749856LL

__device__ float g_scratch[SCRATCH_TOTAL];

// ---------------- mma / ldmatrix helpers ----------------
__device__ __forceinline__ void mma_f16(float c[4],
                                        uint32_t a0, uint32_t a1, uint32_t a2, uint32_t a3,
                                        uint32_t b0, uint32_t b1) {
    asm volatile(
        "mma.sync.aligned.m16n8k16.row.col.f32.f16.f16.f32 "
        "{%0,%1,%2,%3},{%4,%5,%6,%7},{%8,%9},{%0,%1,%2,%3};"
        : "+f"(c[0]), "+f"(c[1]), "+f"(c[2]), "+f"(c[3])
        : "r"(a0), "r"(a1), "r"(a2), "r"(a3), "r"(b0), "r"(b1));
}

__device__ __forceinline__ void ldsm_x4(uint32_t& r0, uint32_t& r1, uint32_t& r2, uint32_t& r3,
                                        uint32_t addr) {
    asm volatile("ldmatrix.sync.aligned.m8n8.x4.shared.b16 {%0,%1,%2,%3}, [%4];"
                 : "=r"(r0), "=r"(r1), "=r"(r2), "=r"(r3) : "r"(addr));
}

__device__ __forceinline__ uint32_t packh2(float lo, float hi) {
    __half2 h = __floats2half2_rn(lo, hi);
    return *(uint32_t*)&h;
}

__device__ __forceinline__ uint32_t smem_u32(const void* p) {
    return (uint32_t)__cvta_generic_to_shared(p);
}

// ============================================================================
// Segmented GEMM: three GEMMs in one launch, 128x64 tiles, 256 thr (8 warps 4x2)
//   seg0 (blk 0..63):    T1XP = gatherN(nf) @ WNT^T   M=2048 N=256 K=512  f32
//   seg1 (blk 64..319):  T2   = gatherE(ef) @ WET^T   M=16384 N=128 K=256 f32
//   seg2 (blk 320..447): QP   = relu(gatherP(ef) @ WE2T^T) M=8192 N=128 K=256 half
// ============================================================================
__global__ __launch_bounds__(256, 2)
void gemm_seg_kernel(const float* __restrict__ nf, const float* __restrict__ ef,
                     const __half* __restrict__ WNT, const __half* __restrict__ WET,
                     const __half* __restrict__ WE2T, const long long* __restrict__ offs,
                     float* __restrict__ T1XP, float* __restrict__ T2, __half* __restrict__ QP)
{
    __shared__ __align__(16) __half As[2][128][24];
    __shared__ __align__(16) __half Bs[2][64][24];

    const int bid = blockIdx.x;
    const float* A; const __half* Bt; float* Cf = nullptr; __half* Ch = nullptr;
    const long long* ro; int K, N, mt, nt, relu = 0;
    if (bid < 64)       { mt = bid >> 2;           nt = bid & 3; K = 512; N = 256; A = nf; Bt = WNT;  Cf = T1XP; ro = offs + LLO_N; }
    else if (bid < 320) { int j = bid - 64;  mt = j >> 1; nt = j & 1; K = 256; N = 128; A = ef; Bt = WET;  Cf = T2;   ro = offs + LLO_E; }
    else                { int j = bid - 320; mt = j >> 1; nt = j & 1; K = 256; N = 128; A = ef; Bt = WE2T; Ch = QP;   ro = offs + LLO_P; relu = 1; }

    const int tile_m = mt * 128;
    const int tile_n = nt * 64;
    const int tid = threadIdx.x;
    const int warp = tid >> 5;
    const int lane = tid & 31;
    const int warp_m = (warp & 3) * 32;
    const int warp_n = (warp >> 2) * 32;

    const int ar = tid >> 1;
    const int ac8 = (tid & 1) * 8;
    long long aoff = ro[tile_m + ar];
    const bool aok = (aoff >= 0);
    const float* apf = A + (aok ? aoff : 0) + ac8;
    const bool bldr = (tid < 128);
    const __half* bp = bldr ? (Bt + (long long)(tile_n + ar) * K + ac8) : Bt;

    const uint32_t a_base = smem_u32(&As[0][0][0]);
    const uint32_t b_base = smem_u32(&Bs[0][0][0]);
    const int li = lane >> 3, lr = lane & 7;
    uint32_t a_addr[2], b_addr[2];
#pragma unroll
    for (int mi = 0; mi < 2; mi++)
        a_addr[mi] = a_base + ((warp_m + mi * 16 + (li & 1) * 8 + lr) * 24 + (li >> 1) * 8) * 2;
#pragma unroll
    for (int j = 0; j < 2; j++)
        b_addr[j] = b_base + ((warp_n + (2 * j + (li >> 1)) * 8 + lr) * 24 + (li & 1) * 8) * 2;

    float acc[2][4][4];
#pragma unroll
    for (int mi = 0; mi < 2; mi++)
#pragma unroll
        for (int ni = 0; ni < 4; ni++)
#pragma unroll
            for (int q = 0; q < 4; q++) acc[mi][ni][q] = 0.f;

    const int nk = K >> 4;
    {
        uint4 ua = make_uint4(0u, 0u, 0u, 0u);
        if (aok) {
            float4 a0 = *(const float4*)(apf);
            float4 a1 = *(const float4*)(apf + 4);
            ua = make_uint4(packh2(a0.x, a0.y), packh2(a0.z, a0.w),
                            packh2(a1.x, a1.y), packh2(a1.z, a1.w));
        }
        *(uint4*)&As[0][ar][ac8] = ua;
        if (bldr) *(uint4*)&Bs[0][ar][ac8] = *(const uint4*)(bp);
    }
    __syncthreads();

    for (int ki = 0; ki < nk; ki++) {
        const int buf = ki & 1;
        const bool more = (ki + 1 < nk);
        float4 pf0, pf1; uint4 pb;
        if (more) {
            const int k0 = (ki + 1) << 4;
            if (aok) { pf0 = *(const float4*)(apf + k0); pf1 = *(const float4*)(apf + k0 + 4); }
            if (bldr) pb = *(const uint4*)(bp + k0);
        }

        uint32_t a[2][4], b[4][2];
        const uint32_t abuf = buf * 6144u, bbuf = buf * 3072u;
#pragma unroll
        for (int mi = 0; mi < 2; mi++)
            ldsm_x4(a[mi][0], a[mi][1], a[mi][2], a[mi][3], a_addr[mi] + abuf);
        ldsm_x4(b[0][0], b[0][1], b[1][0], b[1][1], b_addr[0] + bbuf);
        ldsm_x4(b[2][0], b[2][1], b[3][0], b[3][1], b_addr[1] + bbuf);
#pragma unroll
        for (int mi = 0; mi < 2; mi++)
#pragma unroll
            for (int ni = 0; ni < 4; ni++)
                mma_f16(acc[mi][ni], a[mi][0], a[mi][1], a[mi][2], a[mi][3],
                        b[ni][0], b[ni][1]);

        if (more) {
            const int nb = buf ^ 1;
            uint4 ua = make_uint4(0u, 0u, 0u, 0u);
            if (aok) ua = make_uint4(packh2(pf0.x, pf0.y), packh2(pf0.z, pf0.w),
                                     packh2(pf1.x, pf1.y), packh2(pf1.z, pf1.w));
            *(uint4*)&As[nb][ar][ac8] = ua;
            if (bldr) *(uint4*)&Bs[nb][ar][ac8] = pb;
        }
        __syncthreads();
    }

#pragma unroll
    for (int mi = 0; mi < 2; mi++) {
#pragma unroll
        for (int ni = 0; ni < 4; ni++) {
            const long long row0 = tile_m + warp_m + mi * 16 + (lane >> 2);
            const int col = tile_n + warp_n + ni * 8 + (lane & 3) * 2;
            float v0 = acc[mi][ni][0], v1 = acc[mi][ni][1];
            float v2 = acc[mi][ni][2], v3 = acc[mi][ni][3];
            if (relu) {
                v0 = fmaxf(v0, 0.f); v1 = fmaxf(v1, 0.f);
                v2 = fmaxf(v2, 0.f); v3 = fmaxf(v3, 0.f);
            }
            if (Ch) {
                *(__half2*)&Ch[row0 * N + col] = __floats2half2_rn(v0, v1);
                *(__half2*)&Ch[(row0 + 8) * N + col] = __floats2half2_rn(v2, v3);
            } else {
                *(float2*)&Cf[row0 * N + col] = make_float2(v0, v1);
                *(float2*)&Cf[(row0 + 8) * N + col] = make_float2(v2, v3);
            }
        }
    }
}

// ============================================================================
// HAW GEMM: HAW = HA @ W1AT^T, 2048x768x256, f32 in/out. 128x64 tiles,
// grid (12, 16), 256 thr (8 warps 4x2).
// ============================================================================
__global__ __launch_bounds__(256, 2)
void gemm_haw_kernel(const float* __restrict__ HA, const __half* __restrict__ W1AT,
                     float* __restrict__ HAW)
{
    __shared__ __align__(16) __half As[2][128][24];
    __shared__ __align__(16) __half Bs[2][64][24];

    const int tile_m = blockIdx.y * 128;
    const int tile_n = blockIdx.x * 64;
    const int tid = threadIdx.x;
    const int warp = tid >> 5;
    const int lane = tid & 31;
    const int warp_m = (warp & 3) * 32;
    const int warp_n = (warp >> 2) * 32;

    const int ar = tid >> 1;
    const int ac8 = (tid & 1) * 8;
    const float* apf = HA + (long long)(tile_m + ar) * 256 + ac8;
    const bool bldr = (tid < 128);
    const __half* bp = bldr ? (W1AT + (long long)(tile_n + ar) * 256 + ac8) : W1AT;

    const uint32_t a_base = smem_u32(&As[0][0][0]);
    const uint32_t b_base = smem_u32(&Bs[0][0][0]);
    const int li = lane >> 3, lr = lane & 7;
    uint32_t a_addr[2], b_addr[2];
#pragma unroll
    for (int mi = 0; mi < 2; mi++)
        a_addr[mi] = a_base + ((warp_m + mi * 16 + (li & 1) * 8 + lr) * 24 + (li >> 1) * 8) * 2;
#pragma unroll
    for (int j = 0; j < 2; j++)
        b_addr[j] = b_base + ((warp_n + (2 * j + (li >> 1)) * 8 + lr) * 24 + (li & 1) * 8) * 2;

    float acc[2][4][4];
#pragma unroll
    for (int mi = 0; mi < 2; mi++)
#pragma unroll
        for (int ni = 0; ni < 4; ni++)
#pragma unroll
            for (int q = 0; q < 4; q++) acc[mi][ni][q] = 0.f;

    {
        float4 a0 = *(const float4*)(apf);
        float4 a1 = *(const float4*)(apf + 4);
        *(uint4*)&As[0][ar][ac8] = make_uint4(packh2(a0.x, a0.y), packh2(a0.z, a0.w),
                                              packh2(a1.x, a1.y), packh2(a1.z, a1.w));
        if (bldr) *(uint4*)&Bs[0][ar][ac8] = *(const uint4*)(bp);
    }
    __syncthreads();

    for (int ki = 0; ki < 16; ki++) {
        const int buf = ki & 1;
        const bool more = (ki + 1 < 16);
        float4 pf0, pf1; uint4 pb;
        if (more) {
            const int k0 = (ki + 1) << 4;
            pf0 = *(const float4*)(apf + k0);
            pf1 = *(const float4*)(apf + k0 + 4);
            if (bldr) pb = *(const uint4*)(bp + k0);
        }

        uint32_t a[2][4], b[4][2];
        const uint32_t abuf = buf * 6144u, bbuf = buf * 3072u;
#pragma unroll
        for (int mi = 0; mi < 2; mi++)
            ldsm_x4(a[mi][0], a[mi][1], a[mi][2], a[mi][3], a_addr[mi] + abuf);
        ldsm_x4(b[0][0], b[0][1], b[1][0], b[1][1], b_addr[0] + bbuf);
        ldsm_x4(b[2][0], b[2][1], b[3][0], b[3][1], b_addr[1] + bbuf);
#pragma unroll
        for (int mi = 0; mi < 2; mi++)
#pragma unroll
            for (int ni = 0; ni < 4; ni++)
                mma_f16(acc[mi][ni], a[mi][0], a[mi][1], a[mi][2], a[mi][3],
                        b[ni][0], b[ni][1]);

        if (more) {
            const int nb = buf ^ 1;
            *(uint4*)&As[nb][ar][ac8] = make_uint4(packh2(pf0.x, pf0.y), packh2(pf0.z, pf0.w),
                                                   packh2(pf1.x, pf1.y), packh2(pf1.z, pf1.w));
            if (bldr) *(uint4*)&Bs[nb][ar][ac8] = pb;
        }
        __syncthreads();
    }

#pragma unroll
    for (int mi = 0; mi < 2; mi++) {
#pragma unroll
        for (int ni = 0; ni < 4; ni++) {
            const long long row0 = tile_m + warp_m + mi * 16 + (lane >> 2);
            const int col = tile_n + warp_n + ni * 8 + (lane & 3) * 2;
            *(float2*)&HAW[row0 * 768 + col] = make_float2(acc[mi][ni][0], acc[mi][ni][1]);
            *(float2*)&HAW[(row0 + 8) * 768 + col] = make_float2(acc[mi][ni][2], acc[mi][ni][3]);
        }
    }
}

// ============================================================================
// Pair-level HID GEMM: HID = relu( [Pm|Q] @ W1BT^T + HAW[n0] + HAW[n1] + b1 )
// M=8192, N=768, K=256. A assembled on the fly: Pm = relu(XP[n0]+XP[n1]) (k<128),
// Q = QP[bp] (k>=128). 128x128 tiles, grid (6, 64), 256 thr.
// ============================================================================
__global__ __launch_bounds__(256, 2)
void gemm_hid_kernel(const float* __restrict__ T1XP, const __half* __restrict__ QP,
                     const __half* __restrict__ W1BT, const float* __restrict__ HAW,
                     const float* __restrict__ b1, const int* __restrict__ pairs,
                     __half* __restrict__ HID)
{
    __shared__ __align__(16) __half As[2][128][24];
    __shared__ __align__(16) __half Bs[2][128][24];

    const int tile_m = blockIdx.y * 128;
    const int tile_n = blockIdx.x * 128;
    const int tid = threadIdx.x;
    const int warp = tid >> 5;
    const int lane = tid & 31;
    const int warp_m = (warp & 1) * 64;
    const int warp_n = (warp >> 1) * 32;

    // A loader: assemble [Pm|Q] row bp
    const int ar = tid >> 1;
    const int ac8 = (tid & 1) * 8;
    const int bp_row = tile_m + ar;
    const int bbat = bp_row >> 9;
    const int2 pr = ((const int2*)pairs)[bp_row];
    const float* xp0 = T1XP + ((long long)bbat * 128 + pr.x) * 256 + 128;
    const float* xp1 = T1XP + ((long long)bbat * 128 + pr.y) * 256 + 128;
    const __half* qprow = QP + (long long)bp_row * 128;
    // B loader
    const __half* bpW = W1BT + (long long)(tile_n + ar) * 256 + ac8;

    const uint32_t a_base = smem_u32(&As[0][0][0]);
    const uint32_t b_base = smem_u32(&Bs[0][0][0]);
    const int li = lane >> 3, lr = lane & 7;
    uint32_t a_addr[4], b_addr[2];
#pragma unroll
    for (int mi = 0; mi < 4; mi++)
        a_addr[mi] = a_base + ((warp_m + mi * 16 + (li & 1) * 8 + lr) * 24 + (li >> 1) * 8) * 2;
#pragma unroll
    for (int j = 0; j < 2; j++)
        b_addr[j] = b_base + ((warp_n + (2 * j + (li >> 1)) * 8 + lr) * 24 + (li & 1) * 8) * 2;

    float acc[4][4][4];
#pragma unroll
    for (int mi = 0; mi < 4; mi++)
#pragma unroll
        for (int ni = 0; ni < 4; ni++)
#pragma unroll
            for (int q = 0; q < 4; q++) acc[mi][ni][q] = 0.f;

    // A assembly helper
    auto loadA = [&](int k0) -> uint4 {
        const int c = k0 + ac8;
        if (c < 128) {
            float4 x0a = *(const float4*)(xp0 + c);
            float4 x0b = *(const float4*)(xp0 + c + 4);
            float4 x1a = *(const float4*)(xp1 + c);
            float4 x1b = *(const float4*)(xp1 + c + 4);
            return make_uint4(
                packh2(fmaxf(x0a.x + x1a.x, 0.f), fmaxf(x0a.y + x1a.y, 0.f)),
                packh2(fmaxf(x0a.z + x1a.z, 0.f), fmaxf(x0a.w + x1a.w, 0.f)),
                packh2(fmaxf(x0b.x + x1b.x, 0.f), fmaxf(x0b.y + x1b.y, 0.f)),
                packh2(fmaxf(x0b.z + x1b.z, 0.f), fmaxf(x0b.w + x1b.w, 0.f)));
        } else {
            return *(const uint4*)(qprow + (c - 128));
        }
    };

    *(uint4*)&As[0][ar][ac8] = loadA(0);
    *(uint4*)&Bs[0][ar][ac8] = *(const uint4*)(bpW);
    __syncthreads();

    for (int ki = 0; ki < 16; ki++) {
        const int buf = ki & 1;
        const bool more = (ki + 1 < 16);
        uint4 pa, pb;
        if (more) {
            const int k0 = (ki + 1) << 4;
            pa = loadA(k0);
            pb = *(const uint4*)(bpW + k0);
        }

        uint32_t a[4][4], b[4][2];
        const uint32_t sb = buf * 6144u;
#pragma unroll
        for (int mi = 0; mi < 4; mi++)
            ldsm_x4(a[mi][0], a[mi][1], a[mi][2], a[mi][3], a_addr[mi] + sb);
        ldsm_x4(b[0][0], b[0][1], b[1][0], b[1][1], b_addr[0] + sb);
        ldsm_x4(b[2][0], b[2][1], b[3][0], b[3][1], b_addr[1] + sb);
#pragma unroll
        for (int mi = 0; mi < 4; mi++)
#pragma unroll
            for (int ni = 0; ni < 4; ni++)
                mma_f16(acc[mi][ni], a[mi][0], a[mi][1], a[mi][2], a[mi][3],
                        b[ni][0], b[ni][1]);

        if (more) {
            const int nb = buf ^ 1;
            *(uint4*)&As[nb][ar][ac8] = pa;
            *(uint4*)&Bs[nb][ar][ac8] = pb;
        }
        __syncthreads();
    }

    // epilogue: + HAW[n0] + HAW[n1] + b1, relu, write half
#pragma unroll
    for (int mi = 0; mi < 4; mi++) {
#pragma unroll
        for (int q2 = 0; q2 < 2; q2++) {
            const long long row = tile_m + warp_m + mi * 16 + (lane >> 2) + q2 * 8;
            const int2 prr = ((const int2*)pairs)[row];
            const int bb = (int)(row >> 9);
            const float* h0 = HAW + ((long long)bb * 128 + prr.x) * 768;
            const float* h1 = HAW + ((long long)bb * 128 + prr.y) * 768;
#pragma unroll
            for (int ni = 0; ni < 4; ni++) {
                const int col = tile_n + warp_n + ni * 8 + (lane & 3) * 2;
                float2 g0 = *(const float2*)(h0 + col);
                float2 g1 = *(const float2*)(h1 + col);
                float v0 = acc[mi][ni][q2 * 2 + 0] + g0.x + g1.x + b1[col];
                float v1 = acc[mi][ni][q2 * 2 + 1] + g0.y + g1.y + b1[col + 1];
                *(__half2*)&HID[row * 768 + col] =
                    __floats2half2_rn(fmaxf(v0, 0.f), fmaxf(v1, 0.f));
            }
        }
    }
}

// ============================================================================
// Layer-2 GEMM: out = HID @ W2T^T + b2, 8192x32x768, block-diag W2, scatter epi
// ============================================================================
__global__ __launch_bounds__(128)
void gemm_l2_kernel(const __half* __restrict__ HID, const __half* __restrict__ W2T,
                    const float* __restrict__ b2, float* __restrict__ out)
{
    __shared__ __align__(16) __half As[2][64][24];
    __shared__ __align__(16) __half Bs[2][32][24];

    const int tile_m = blockIdx.x * 64;
    const int tid = threadIdx.x;
    const int warp = tid >> 5;
    const int lane = tid & 31;
    const int warp_m = warp * 16;

    const int ar = tid >> 1;
    const int ac8 = (tid & 1) * 8;
    const __half* ap = HID + (long long)(tile_m + ar) * 768 + ac8;
    const bool bldr = (tid < 64);
    const __half* bp = bldr ? (W2T + (long long)ar * 768 + ac8) : W2T;

    const uint32_t a_base = smem_u32(&As[0][0][0]);
    const uint32_t b_base = smem_u32(&Bs[0][0][0]);
    const int li = lane >> 3, lr = lane & 7;
    const uint32_t a_addr = a_base + ((warp_m + (li & 1) * 8 + lr) * 24 + (li >> 1) * 8) * 2;
    uint32_t b_addr[2];
#pragma unroll
    for (int j = 0; j < 2; j++)
        b_addr[j] = b_base + (((2 * j + (li >> 1)) * 8 + lr) * 24 + (li & 1) * 8) * 2;

    float acc[4][4];
#pragma unroll
    for (int ni = 0; ni < 4; ni++)
#pragma unroll
        for (int q = 0; q < 4; q++) acc[ni][q] = 0.f;

    *(uint4*)&As[0][ar][ac8] = *(const uint4*)(ap);
    if (bldr) *(uint4*)&Bs[0][ar][ac8] = *(const uint4*)(bp);
    __syncthreads();

    for (int ki = 0; ki < 48; ki++) {
        const int buf = ki & 1;
        const bool more = (ki + 1 < 48);
        uint4 pa, pb;
        if (more) {
            const int k0 = (ki + 1) << 4;
            pa = *(const uint4*)(ap + k0);
            if (bldr) pb = *(const uint4*)(bp + k0);
        }

        uint32_t a[4], b[4][2];
        const uint32_t asb = buf * 3072u, bsb = buf * 1536u;
        ldsm_x4(a[0], a[1], a[2], a[3], a_addr + asb);
        ldsm_x4(b[0][0], b[0][1], b[1][0], b[1][1], b_addr[0] + bsb);
        ldsm_x4(b[2][0], b[2][1], b[3][0], b[3][1], b_addr[1] + bsb);
#pragma unroll
        for (int ni = 0; ni < 4; ni++)
            mma_f16(acc[ni], a[0], a[1], a[2], a[3], b[ni][0], b[ni][1]);

        if (more) {
            const int nb = buf ^ 1;
            *(uint4*)&As[nb][ar][ac8] = pa;
            if (bldr) *(uint4*)&Bs[nb][ar][ac8] = pb;
        }
        __syncthreads();
    }

    float* out_cr = out + (long long)Bb * Pp * LR_OUT;
    float* out_mr = out_cr + (long long)Bb * Pp * CR_OUT;
#pragma unroll
    for (int ni = 0; ni < 4; ni++) {
        const long long r0 = tile_m + warp_m + (lane >> 2);
        const int c0 = ni * 8 + (lane & 3) * 2;
#pragma unroll
        for (int q = 0; q < 4; q++) {
            const long long row = r0 + (q >> 1) * 8;
            const int c = c0 + (q & 1);
            const float v = acc[ni][q] + b2[c];
            if (c < 9)       out[row * 9 + c] = v;
            else if (c < 15) out_cr[row * 6 + (c - 9)] = v;
            else             out_mr[row * 17 + (c - 15)] = v;
        }
    }
}

// ---------------- prep ----------------
#define PRE_OFFE 2048
#define PRE_OFFP 18432
#define PRE_WNT  26624
#define PRE_WET  157696
#define PRE_WE2T 190464
#define PRE_W1AT 223232
#define PRE_W1BT 419840
#define PRE_W2T  616448
#define PRE_B1   641024
#define PRE_B2   641792
#define PRE_HA   641824
#define PRE_TOT  1166112

__global__ void prep_kernel(const int* __restrict__ eidx, const int* __restrict__ pairs,
                            const int* __restrict__ num_obj, const int* __restrict__ num_edges,
                            const float* __restrict__ Wn, const float* __restrict__ Wn2,
                            const float* __restrict__ We, const float* __restrict__ We2,
                            const float* __restrict__ lrW1, const float* __restrict__ scrW1,
                            const float* __restrict__ mrW1,
                            const float* __restrict__ lrb1, const float* __restrict__ scrb1,
                            const float* __restrict__ mrb1,
                            const float* __restrict__ lrW2, const float* __restrict__ scrW2,
                            const float* __restrict__ mrW2,
                            const float* __restrict__ lrb2, const float* __restrict__ scrb2,
                            const float* __restrict__ mrb2,
                            long long* __restrict__ offs,
                            __half* __restrict__ WNT, __half* __restrict__ WET,
                            __half* __restrict__ WE2T, __half* __restrict__ W1AT,
                            __half* __restrict__ W1BT, __half* __restrict__ W2T,
                            float* __restrict__ b1c, float* __restrict__ b2c,
                            float* __restrict__ HA)
{
    int t = blockIdx.x * blockDim.x + threadIdx.x;
    if (t >= PRE_TOT) return;
    if (t < PRE_OFFE) {
        int b = t >> 7, r = t & 127;
        offs[LLO_N + t] = (r < num_obj[b]) ? (long long)t * DNd : -1LL;
    } else if (t < PRE_OFFP) {
        int j = t - PRE_OFFE;
        int b = j >> 10, m = j & 1023;
        long long v = -1LL;
        if (m < num_edges[b]) {
            int s = eidx[b * 2 * Mm + m];
            int d = eidx[b * 2 * Mm + Mm + m];
            v = (((long long)b * Nn + s) * Nn + d) * DEe;
        }
        offs[LLO_E + j] = v;
    } else if (t < PRE_WNT) {
        int j = t - PRE_OFFP;
        int b = j >> 9;
        int n0 = pairs[(long long)j * 2 + 0];
        int n1 = pairs[(long long)j * 2 + 1];
        offs[LLO_P + j] = (((long long)b * Nn + n0) * Nn + n1) * DEe;
    } else if (t < PRE_WET) {                        // [Wn|Wn2]^T half [256][512]
        int j = t - PRE_WNT;
        int c = j >> 9, k = j & 511;
        float v = (c < 128) ? Wn[k * 128 + c] : Wn2[k * 128 + (c - 128)];
        WNT[j] = __float2half(v);
    } else if (t < PRE_WE2T) {                       // We^T half [128][256]
        int j = t - PRE_WET;
        int c = j >> 8, k = j & 255;
        WET[j] = __float2half(We[k * 128 + c]);
    } else if (t < PRE_W1AT) {                       // We2^T half [128][256]
        int j = t - PRE_WE2T;
        int c = j >> 8, k = j & 255;
        WE2T[j] = __float2half(We2[k * 128 + c]);
    } else if (t < PRE_W1BT) {                       // W1 rows 0:256 ^T half [768][256]
        int j = t - PRE_W1AT;
        int c = j >> 8, k = j & 255;                 // k in [0,256)
        float v;
        if (c < 256) v = lrW1[k * 256 + c];
        else if (c < 512) v = scrW1[k * 256 + (c - 256)];
        else v = mrW1[k * 256 + (c - 512)];
        W1AT[j] = __float2half(v);
    } else if (t < PRE_W2T) {                        // W1 rows 256:512 ^T half [768][256]
        int j = t - PRE_W1BT;
        int c = j >> 8, k = (j & 255) + 256;         // k in [256,512)
        float v;
        if (c < 256) v = lrW1[k * 256 + c];
        else if (c < 512) v = scrW1[k * 256 + (c - 256)];
        else v = mrW1[k * 256 + (c - 512)];
        W1BT[j] = __float2half(v);
    } else if (t < PRE_B1) {                         // block-diag W2^T half [32][768]
        int j = t - PRE_W2T;
        int c = j / 768, k = j % 768;
        float v = 0.f;
        if (c < 9)       { if (k < 256)             v = lrW2[k * 9 + c]; }
        else if (c < 15) { if (k >= 256 && k < 512) v = scrW2[(k - 256) * 6 + (c - 9)]; }
        else             { if (k >= 512)            v = mrW2[(k - 512) * 17 + (c - 15)]; }
        W2T[j] = __float2half(v);
    } else if (t < PRE_B2) {
        int j = t - PRE_B1;
        b1c[j] = (j < 256) ? lrb1[j] : (j < 512 ? scrb1[j - 256] : mrb1[j - 512]);
    } else if (t < PRE_HA) {
        int j = t - PRE_B2;
        b2c[j] = (j < 9) ? lrb2[j] : (j < 15 ? scrb2[j - 9] : mrb2[j - 15]);
    } else {
        HA[t - PRE_HA] = 0.f;
    }
}

// ---------------- merged sparse propagation (node + line graph) ----------------
// node part: HA[b*128+r][0:128]   = rowmask(relu((adj+I)@T1))
// line part: HA[b*128+src][128:256] += relu((ladj+I)@T2)  (src < num_obj only)
__global__ void prop_all_kernel(const float* __restrict__ adj, const float* __restrict__ t1xp,
                                float* __restrict__ HA, const int* __restrict__ num_obj,
                                const float* __restrict__ ladj, const float* __restrict__ T2,
                                const int* __restrict__ eidx, const int* __restrict__ num_edges)
{
    __shared__ int s_idx[1024];
    __shared__ float s_val[1024];
    __shared__ int s_cnt;
    const int t = threadIdx.x;

    if (blockIdx.x < 2048) {
        int b = blockIdx.x >> 7;
        int r = blockIdx.x & 127;
        int lim = num_obj[b];
        if (r >= lim) return;   // HA pre-zeroed
        if (t == 0) s_cnt = 0;
        __syncthreads();
        float a = adj[(((long long)b * 128) + r) * 128 + t];
        if (a != 0.f) {
            int p = atomicAdd(&s_cnt, 1);
            s_idx[p] = t; s_val[p] = a;
        }
        __syncthreads();
        const float* Tb = t1xp + (long long)b * 128 * 256;
        float acc = Tb[r * 256 + t];
        int n = s_cnt;
        for (int i = 0; i < n; i++)
            acc = fmaf(s_val[i], Tb[s_idx[i] * 256 + t], acc);
        HA[((long long)b * 128 + r) * 256 + t] = fmaxf(acc, 0.f);
    } else {
        int j = blockIdx.x - 2048;
        int b = j >> 10;
        int m = j & 1023;
        if (m >= num_edges[b]) return;
        int s = eidx[b * 2 * Mm + m];
        if (s >= num_obj[b]) return;   // reference zeroes agg rows >= num_obj
        if (t == 0) s_cnt = 0;
        __syncthreads();
        const float4* lrow4 = (const float4*)(ladj + (((long long)b * 1024) + m) * 1024);
#pragma unroll
        for (int jj = 0; jj < 2; jj++) {
            int base = (t * 2 + jj) * 4;
            float4 v = lrow4[t * 2 + jj];
            float vv[4] = {v.x, v.y, v.z, v.w};
#pragma unroll
            for (int e = 0; e < 4; e++) {
                if (vv[e] != 0.f) {
                    int p = atomicAdd(&s_cnt, 1);
                    s_idx[p] = base + e; s_val[p] = vv[e];
                }
            }
        }
        __syncthreads();
        const float* Tb = T2 + (long long)b * 1024 * 128;
        float acc = Tb[m * 128 + t];
        int n = s_cnt;
        for (int i = 0; i < n; i++)
            acc = fmaf(s_val[i], Tb[s_idx[i] * 128 + t], acc);
        acc = fmaxf(acc, 0.f);
        atomicAdd(&HA[((long long)b * 128 + s) * 256 + 128 + t], acc);
    }
}

// ---------------- launch ----------------
extern "C" void kernel_launch(void* const* d_in, const int* in_sizes, int n_in,
                              void* d_out, int out_size)
{
    const float* node_features = (const float*)d_in[0];
    const float* edge_features = (const float*)d_in[1];
    const float* adj           = (const float*)d_in[2];
    const float* ladj          = (const float*)d_in[3];
    const int*   edge_index    = (const int*)d_in[4];
    const int*   pairs         = (const int*)d_in[5];
    const int*   num_obj       = (const int*)d_in[6];
    const int*   num_edges     = (const int*)d_in[7];
    const float* Wn  = (const float*)d_in[8];
    const float* We  = (const float*)d_in[9];
    const float* Wn2 = (const float*)d_in[10];
    const float* We2 = (const float*)d_in[11];
    const float* scr_W1 = (const float*)d_in[12];
    const float* scr_b1 = (const float*)d_in[13];
    const float* scr_W2 = (const float*)d_in[14];
    const float* scr_b2 = (const float*)d_in[15];
    const float* lr_W1 = (const float*)d_in[16];
    const float* lr_b1 = (const float*)d_in[17];
    const float* lr_W2 = (const float*)d_in[18];
    const float* lr_b2 = (const float*)d_in[19];
    const float* mr_W1 = (const float*)d_in[20];
    const float* mr_b1 = (const float*)d_in[21];
    const float* mr_W2 = (const float*)d_in[22];
    const float* mr_b2 = (const float*)d_in[23];

    float* out = (float*)d_out;

    float* sc = nullptr;
    cudaGetSymbolAddress((void**)&sc, g_scratch);

    long long* OFFS = (long long*)(sc + OFF_OFFS);
    float*  T1XP = sc + OFF_T1XP;
    float*  T2   = sc + OFF_T2;
    float*  HA   = sc + OFF_HA;
    float*  HAW  = sc + OFF_HAW;
    __half* QPh  = (__half*)(sc + OFF_QP);
    __half* HIDh = (__half*)(sc + OFF_HID);
    __half* WNT  = (__half*)(sc + OFF_WNT);
    __half* WET  = (__half*)(sc + OFF_WET);
    __half* WE2T = (__half*)(sc + OFF_WE2T);
    __half* W1AT = (__half*)(sc + OFF_W1AT);
    __half* W1BT = (__half*)(sc + OFF_W1BT);
    __half* W2T  = (__half*)(sc + OFF_W2T);
    float*  B1C  = sc + OFF_B1C;
    float*  B2C  = sc + OFF_B2C;

    // 1. prep: offsets + packed/transposed half weights + biases + HA zero
    prep_kernel<<<(PRE_TOT + 255) / 256, 256>>>(
        edge_index, pairs, num_obj, num_edges,
        Wn, Wn2, We, We2, lr_W1, scr_W1, mr_W1, lr_b1, scr_b1, mr_b1,
        lr_W2, scr_W2, mr_W2, lr_b2, scr_b2, mr_b2,
        OFFS, WNT, WET, WE2T, W1AT, W1BT, W2T, B1C, B2C, HA);

    // 2. segmented GEMM: T1XP + T2 + QP in one wave
    gemm_seg_kernel<<<448, 256>>>(
        node_features, edge_features, WNT, WET, WE2T, OFFS, T1XP, T2, QPh);

    // 3. merged sparse propagation into HA = [H | AGG]
    prop_all_kernel<<<2048 + Bb * Mm, 128>>>(
        adj, T1XP, HA, num_obj, ladj, T2, edge_index, num_edges);

    // 4. HAW = HA @ W1[0:256]   (2048 x 768 x 256)
    gemm_haw_kernel<<<dim3(12, 16), 256>>>(HA, W1AT, HAW);

    // 5. pair HID = relu([Pm|Q] @ W1[256:512] + HAW[n0] + HAW[n1] + b1)
    gemm_hid_kernel<<<dim3(6, 64), 256>>>(T1XP, QPh, W1BT, HAW, B1C, pairs, HIDh);

    // 6. layer-2 GEMM (8192 x 32 x 768, block-diag) with scatter epilogue
    gemm_l2_kernel<<<128, 128>>>(HIDh, W2T, B2C, out);
}